// round 3
// baseline (speedup 1.0000x reference)
#include <cuda_runtime.h>
#include <cstdint>

#define H 256
#define W 256
#define K 512
#define Z_THRESHOLD 3.0f
#define EPS 1e-08f

// sqrt(0.5 * log2(e)): folded into inverse scales so gauss = exp2(-(dx'^2+dy'^2))
#define SCALE_C 0.84932180028801904f

#define CHUNKS 4          // threads cooperating per pixel
#define RBLOCK 256        // render block size

// Sorted gaussian parameter scratch (device globals: no allocation allowed)
__device__ float4 g_pack4[K];  // px, py, isx*C, isy*C
__device__ float2 g_pack2[K];  // eff_w, intensity
__device__ int    g_M;

// ---------------------------------------------------------------------------
// Kernel 1: compute eff_w, stable-sort descending by eff_w (register bitonic:
// shuffles for j<32, smem for the 10 cross-warp phases), pack params in
// sorted order, count nonzero prefix. One block, K threads.
// ---------------------------------------------------------------------------
__global__ void __launch_bounds__(K, 1)
prep_kernel(const float* __restrict__ positions,   // [K,3]
            const float* __restrict__ scales,      // [K,3]
            const float* __restrict__ opacity,     // [K]
            const float* __restrict__ intensity,   // [K]
            const float* __restrict__ z_target)    // [1]
{
    const int tid = threadIdx.x;

    const float zt = z_target[0];
    const float pz = positions[tid * 3 + 2];
    const float sz = scales[tid * 3 + 2];
    const float zd = (zt - pz) / (sz + EPS);
    float w = 0.0f;
    if (fabsf(zd) < Z_THRESHOLD) {
        w = opacity[tid] * __expf(-0.5f * zd * zd);
    }

    // Pack: ascending uint64 sort == descending eff_w, ascending idx on ties
    // (matches stable jnp.argsort(-eff_w); keys unique via embedded idx).
    unsigned int wb = __float_as_uint(w);   // w >= 0 so bits are monotone
    unsigned long long key =
        ((unsigned long long)(~wb) << 32) | (unsigned int)tid;

    __shared__ unsigned long long sk[K];

    // Bitonic sort, ascending, register-resident.
    for (int k = 2; k <= K; k <<= 1) {
        for (int j = k >> 1; j > 0; j >>= 1) {
            unsigned long long b;
            if (j >= 32) {
                sk[tid] = key;
                __syncthreads();
                b = sk[tid ^ j];
                __syncthreads();
            } else {
                b = __shfl_xor_sync(0xFFFFFFFFu, key, j);
            }
            bool up      = ((tid & k) == 0);
            bool lower   = ((tid & j) == 0);
            bool keepMin = (up == lower);
            key = ((key < b) == keepMin) ? key : b;
        }
    }

    int src = (int)(key & 0xFFFFFFFFull);
    float wsorted = __uint_as_float(~(unsigned int)(key >> 32));

    float4 p4;
    p4.x = positions[src * 3 + 0];
    p4.y = positions[src * 3 + 1];
    p4.z = SCALE_C / (scales[src * 3 + 0] + EPS);
    p4.w = SCALE_C / (scales[src * 3 + 1] + EPS);
    g_pack4[tid] = p4;
    g_pack2[tid] = make_float2(wsorted, intensity[src]);

    // Zeros sort to the end and are compositing identities; renderer stops at M.
    int cnt = __syncthreads_count(wsorted > 0.0f);
    if (tid == 0) g_M = cnt;
}

// ---------------------------------------------------------------------------
// Kernel 2: 4 threads per pixel, each compositing a contiguous chunk of the
// sorted gaussian list, merged with the associative over-operator via
// shfl_xor:  A = A_early + T_early * A_late,  T = T_early * T_late.
// ---------------------------------------------------------------------------
__global__ void __launch_bounds__(RBLOCK)
render_kernel(float* __restrict__ out)
{
    __shared__ float4 sp[K];
    __shared__ float2 swi[K];

    const int tid = threadIdx.x;
    const int M = g_M;

    for (int i = tid; i < M; i += RBLOCK) {
        sp[i]  = g_pack4[i];
        swi[i] = g_pack2[i];
    }
    __syncthreads();

    const int g     = blockIdx.x * RBLOCK + tid;
    const int pixel = g >> 2;           // 4 consecutive lanes share a pixel
    const int chunk = g & 3;

    const float fy = (float)(pixel >> 8);   // row (positions[:,0])
    const float fx = (float)(pixel & 255);  // col (positions[:,1])

    const int chunkLen = (M + CHUNKS - 1) >> 2;
    int lo = chunk * chunkLen; if (lo > M) lo = M;
    int hi = lo + chunkLen;    if (hi > M) hi = M;

    float T = 1.0f;
    float A = 0.0f;

    #pragma unroll 4
    for (int j = lo; j < hi; ++j) {
        const float4 P  = sp[j];
        const float2 WI = swi[j];

        float dx   = (fy - P.x) * P.z;
        float ndx2 = -dx * dx;
        float dy   = (fx - P.y) * P.w;
        float arg  = fmaf(dy, -dy, ndx2);     // -(dx'^2 + dy'^2)

        float gg;
        asm("ex2.approx.ftz.f32 %0, %1;" : "=f"(gg) : "f"(arg));

        float a  = fminf(gg * WI.x, 0.99f);
        float ta = T * a;
        A = fmaf(ta, WI.y, A);
        T -= ta;
    }

    // Merge the 4 chunk results (front-to-back composition is associative).
    #pragma unroll
    for (int s = 1; s < CHUNKS; s <<= 1) {
        float Tp = __shfl_xor_sync(0xFFFFFFFFu, T, s);
        float Ap = __shfl_xor_sync(0xFFFFFFFFu, A, s);
        bool earlier = ((chunk & s) == 0);
        float Te = earlier ? T  : Tp;
        float Ae = earlier ? A  : Ap;
        float Tl = earlier ? Tp : T;
        float Al = earlier ? Ap : A;
        A = fmaf(Te, Al, Ae);
        T = Te * Tl;
    }

    if (chunk == 0) out[pixel] = A;
}

extern "C" void kernel_launch(void* const* d_in, const int* in_sizes, int n_in,
                              void* d_out, int out_size)
{
    const float* positions = (const float*)d_in[0];
    const float* scales    = (const float*)d_in[1];
    const float* opacity   = (const float*)d_in[2];
    const float* intensity = (const float*)d_in[3];
    const float* z_target  = (const float*)d_in[4];
    float* out = (float*)d_out;

    prep_kernel<<<1, K>>>(positions, scales, opacity, intensity, z_target);
    render_kernel<<<(H * W * CHUNKS) / RBLOCK, RBLOCK>>>(out);
}

// round 4
// speedup vs baseline: 1.1582x; 1.1582x over previous
#include <cuda_runtime.h>
#include <cstdint>

#define H 256
#define W 256
#define K 512
#define Z_THRESHOLD 3.0f
#define EPS 1e-08f

// sqrt(0.5 * log2(e)): folded into inverse scales so gauss = exp2(-(dx'^2+dy'^2))
#define SCALE_C 0.84932180028801904f

#define CHUNKS 4          // warp-groups cooperating per pixel block
#define RBLOCK 256        // render block size (4 groups x 64 threads)
#define PXB    128        // pixels per block (2 px per thread)

// Sorted gaussian parameter scratch (device globals: no allocation allowed)
__device__ float4 g_pack4[K];  // px, py, isx*C, isy*C
__device__ float2 g_pack2[K];  // eff_w, intensity
__device__ int    g_M;

// ---------------------------------------------------------------------------
// Kernel 1: compute eff_w, stable-sort descending by eff_w (register bitonic:
// shuffles for j<32, smem for the 10 cross-warp phases), pack params in
// sorted order, count nonzero prefix. One block, K threads.
// ---------------------------------------------------------------------------
__global__ void __launch_bounds__(K, 1)
prep_kernel(const float* __restrict__ positions,   // [K,3]
            const float* __restrict__ scales,      // [K,3]
            const float* __restrict__ opacity,     // [K]
            const float* __restrict__ intensity,   // [K]
            const float* __restrict__ z_target)    // [1]
{
    const int tid = threadIdx.x;

    const float zt = z_target[0];
    const float pz = positions[tid * 3 + 2];
    const float sz = scales[tid * 3 + 2];
    const float zd = (zt - pz) / (sz + EPS);
    float w = 0.0f;
    if (fabsf(zd) < Z_THRESHOLD) {
        w = opacity[tid] * __expf(-0.5f * zd * zd);
    }

    // Pack: ascending uint64 sort == descending eff_w, ascending idx on ties
    // (matches stable jnp.argsort(-eff_w); keys unique via embedded idx).
    unsigned int wb = __float_as_uint(w);   // w >= 0 so bits are monotone
    unsigned long long key =
        ((unsigned long long)(~wb) << 32) | (unsigned int)tid;

    __shared__ unsigned long long sk[K];

    // Bitonic sort, ascending, register-resident.
    for (int k = 2; k <= K; k <<= 1) {
        for (int j = k >> 1; j > 0; j >>= 1) {
            unsigned long long b;
            if (j >= 32) {
                sk[tid] = key;
                __syncthreads();
                b = sk[tid ^ j];
                __syncthreads();
            } else {
                b = __shfl_xor_sync(0xFFFFFFFFu, key, j);
            }
            bool up      = ((tid & k) == 0);
            bool lower   = ((tid & j) == 0);
            bool keepMin = (up == lower);
            key = ((key < b) == keepMin) ? key : b;
        }
    }

    int src = (int)(key & 0xFFFFFFFFull);
    float wsorted = __uint_as_float(~(unsigned int)(key >> 32));

    float4 p4;
    p4.x = positions[src * 3 + 0];
    p4.y = positions[src * 3 + 1];
    p4.z = SCALE_C / (scales[src * 3 + 0] + EPS);
    p4.w = SCALE_C / (scales[src * 3 + 1] + EPS);
    g_pack4[tid] = p4;
    g_pack2[tid] = make_float2(wsorted, intensity[src]);

    // Zeros sort to the end and are compositing identities; renderer stops at M.
    int cnt = __syncthreads_count(wsorted > 0.0f);
    if (tid == 0) g_M = cnt;
}

// ---------------------------------------------------------------------------
// Kernel 2: block = 128 pixels (half a row). 4 warp-groups of 64 threads each
// composite one contiguous quarter of the sorted gaussian list over those
// pixels (2 px/thread, gaussian index warp-uniform -> broadcast LDS).
// Chunks merged through smem: A = A0 + T0*(A1 + T1*(A2 + T2*A3)).
// ---------------------------------------------------------------------------
__global__ void __launch_bounds__(RBLOCK)
render_kernel(float* __restrict__ out)
{
    __shared__ float4 sp[K];
    __shared__ float2 swi[K];
    __shared__ float  sT[CHUNKS][PXB];
    __shared__ float  sA[CHUNKS][PXB];

    const int tid = threadIdx.x;
    const int M = g_M;

    for (int i = tid; i < M; i += RBLOCK) {
        sp[i]  = g_pack4[i];
        swi[i] = g_pack2[i];
    }
    __syncthreads();

    const int chunk = tid >> 6;          // warp-uniform (2 warps per chunk)
    const int sub   = tid & 63;          // thread within chunk group
    const int px0   = 2 * sub;           // local pixel pair

    // Block covers pixels [blockIdx*128, blockIdx*128+128): half of one row.
    const float fy  = (float)(blockIdx.x >> 1);                    // row
    const float fx0 = (float)(((blockIdx.x & 1) << 7) + px0);      // col

    const int chunkLen = (M + CHUNKS - 1) >> 2;
    int lo = chunk * chunkLen; if (lo > M) lo = M;
    int hi = lo + chunkLen;    if (hi > M) hi = M;

    float T0 = 1.0f, T1 = 1.0f;
    float A0 = 0.0f, A1 = 0.0f;

    #pragma unroll 4
    for (int j = lo; j < hi; ++j) {
        const float4 P  = sp[j];
        const float2 WI = swi[j];

        float dx   = (fy - P.x) * P.z;
        float ndx2 = -dx * dx;
        float dy0  = (fx0 - P.y) * P.w;
        float dy1  = dy0 + P.w;                 // fx1 = fx0 + 1

        float arg0 = fmaf(dy0, -dy0, ndx2);     // -(dx'^2 + dy'^2)
        float arg1 = fmaf(dy1, -dy1, ndx2);

        float gg0, gg1;
        asm("ex2.approx.ftz.f32 %0, %1;" : "=f"(gg0) : "f"(arg0));
        asm("ex2.approx.ftz.f32 %0, %1;" : "=f"(gg1) : "f"(arg1));

        float a0 = fminf(gg0 * WI.x, 0.99f);
        float a1 = fminf(gg1 * WI.x, 0.99f);

        float ta0 = T0 * a0;
        float ta1 = T1 * a1;
        A0 = fmaf(ta0, WI.y, A0);
        A1 = fmaf(ta1, WI.y, A1);
        T0 -= ta0;
        T1 -= ta1;
    }

    sT[chunk][px0]     = T0;
    sT[chunk][px0 + 1] = T1;
    sA[chunk][px0]     = A0;
    sA[chunk][px0 + 1] = A1;
    __syncthreads();

    // First 128 threads: merge the 4 chunks for one pixel each.
    if (tid < PXB) {
        float a0 = sA[0][tid], a1 = sA[1][tid], a2 = sA[2][tid], a3 = sA[3][tid];
        float t0 = sT[0][tid], t1 = sT[1][tid], t2 = sT[2][tid];
        float A = fmaf(t0, fmaf(t1, fmaf(t2, a3, a2), a1), a0);
        out[blockIdx.x * PXB + tid] = A;
    }
}

extern "C" void kernel_launch(void* const* d_in, const int* in_sizes, int n_in,
                              void* d_out, int out_size)
{
    const float* positions = (const float*)d_in[0];
    const float* scales    = (const float*)d_in[1];
    const float* opacity   = (const float*)d_in[2];
    const float* intensity = (const float*)d_in[3];
    const float* z_target  = (const float*)d_in[4];
    float* out = (float*)d_out;

    prep_kernel<<<1, K>>>(positions, scales, opacity, intensity, z_target);
    render_kernel<<<(H * W) / PXB, RBLOCK>>>(out);
}

// round 5
// speedup vs baseline: 1.4317x; 1.2362x over previous
#include <cuda_runtime.h>
#include <cstdint>

#define H 256
#define W 256
#define K 512
#define Z_THRESHOLD 3.0f
#define EPS 1e-08f

// sqrt(0.5 * log2(e)): folded into inverse scales so gauss = exp2(-(dx'^2+dy'^2))
#define SCALE_C 0.84932180028801904f

#define TPB  512            // threads per block == K
#define GRID ((H * W) / TPB)  // 128 blocks, one pixel per thread, single wave

// ---------------------------------------------------------------------------
// Fused kernel: every block redundantly preps (eff_w + stable descending sort
// of all K gaussians, register bitonic) in shared memory, then each thread
// composites one pixel front-to-back over the M active sorted gaussians.
// One wave (128 blocks < #SMs), one launch, no global round-trip.
// ---------------------------------------------------------------------------
__global__ void __launch_bounds__(TPB, 1)
fused_kernel(const float* __restrict__ positions,   // [K,3]
             const float* __restrict__ scales,      // [K,3]
             const float* __restrict__ opacity,     // [K]
             const float* __restrict__ intensity,   // [K]
             const float* __restrict__ z_target,    // [1]
             float* __restrict__ out)               // [H*W]
{
    __shared__ unsigned long long sk[K];
    __shared__ float4 up4[K];   // unsorted: isx, -px*isx, isy, -py*isy
    __shared__ float  uin[K];   // unsorted intensity
    __shared__ float4 sp[K];    // sorted params
    __shared__ float2 swi[K];   // sorted (eff_w, intensity)
    __shared__ int    sM;

    const int tid = threadIdx.x;

    // ---- prep: per-gaussian weight + packed params (unsorted) ----
    const float zt  = z_target[0];
    const float px  = positions[tid * 3 + 0];
    const float py  = positions[tid * 3 + 1];
    const float pz  = positions[tid * 3 + 2];
    const float isx = SCALE_C / (scales[tid * 3 + 0] + EPS);
    const float isy = SCALE_C / (scales[tid * 3 + 1] + EPS);
    const float sz  = scales[tid * 3 + 2];

    const float zd = (zt - pz) / (sz + EPS);
    float w = 0.0f;
    if (fabsf(zd) < Z_THRESHOLD) {
        w = opacity[tid] * __expf(-0.5f * zd * zd);
    }

    up4[tid] = make_float4(isx, -px * isx, isy, -py * isy);
    uin[tid] = intensity[tid];

    // Pack: ascending uint64 sort == descending eff_w, ascending idx on ties
    // (matches stable jnp.argsort(-eff_w); keys unique via embedded idx).
    unsigned int wb = __float_as_uint(w);   // w >= 0 so bits are monotone
    unsigned long long key =
        ((unsigned long long)(~wb) << 32) | (unsigned int)tid;

    __syncthreads();   // up4/uin visible before post-sort gather

    // ---- bitonic sort, ascending, register-resident ----
    for (int k = 2; k <= K; k <<= 1) {
        for (int j = k >> 1; j > 0; j >>= 1) {
            unsigned long long b;
            if (j >= 32) {
                sk[tid] = key;
                __syncthreads();
                b = sk[tid ^ j];
                __syncthreads();
            } else {
                b = __shfl_xor_sync(0xFFFFFFFFu, key, j);
            }
            bool up      = ((tid & k) == 0);
            bool lower   = ((tid & j) == 0);
            bool keepMin = (up == lower);
            key = ((key < b) == keepMin) ? key : b;
        }
    }

    const int src = (int)(key & 0xFFFFFFFFull);
    const float wsorted = __uint_as_float(~(unsigned int)(key >> 32));

    sp[tid]  = up4[src];
    swi[tid] = make_float2(wsorted, uin[src]);

    // Zeros sort to the end and are compositing identities; stop at M.
    int cnt = __syncthreads_count(wsorted > 0.0f);
    if (tid == 0) sM = cnt;
    __syncthreads();

    // ---- render: one pixel per thread ----
    const int M = sM;
    const int p = blockIdx.x * TPB + tid;
    const float fy = (float)(p >> 8);    // row    (positions[:,0])
    const float fx = (float)(p & 255);   // column (positions[:,1])

    float T = 1.0f;
    float A = 0.0f;

    #pragma unroll 4
    for (int j = 0; j < M; ++j) {
        const float4 P  = sp[j];
        const float2 WI = swi[j];

        float dx   = fmaf(fy, P.x, P.y);      // (fy - px) * isx
        float dy   = fmaf(fx, P.z, P.w);      // (fx - py) * isy
        float ndx2 = -dx * dx;
        float arg  = fmaf(dy, -dy, ndx2);     // -(dx'^2 + dy'^2)

        float gg;
        asm("ex2.approx.ftz.f32 %0, %1;" : "=f"(gg) : "f"(arg));

        float a  = fminf(gg * WI.x, 0.99f);
        float ta = T * a;
        A = fmaf(ta, WI.y, A);
        T -= ta;
    }

    out[p] = A;
}

extern "C" void kernel_launch(void* const* d_in, const int* in_sizes, int n_in,
                              void* d_out, int out_size)
{
    const float* positions = (const float*)d_in[0];
    const float* scales    = (const float*)d_in[1];
    const float* opacity   = (const float*)d_in[2];
    const float* intensity = (const float*)d_in[3];
    const float* z_target  = (const float*)d_in[4];
    float* out = (float*)d_out;

    fused_kernel<<<GRID, TPB>>>(positions, scales, opacity, intensity,
                                z_target, out);
}